// round 10
// baseline (speedup 1.0000x reference)
#include <cuda_runtime.h>
#include <cuda_bf16.h>
#include <cstdint>

#define FULL_MASK 0xFFFFFFFFu

constexpr int E_EDGES = 65536;
constexpr int F_DIM   = 128;
constexpr int D_DEG   = 32;
constexpr int BLOCKS  = 592;       // 148 SMs x 4 resident blocks = one wave
constexpr int THREADS = 256;
constexpr int N_WARPS = BLOCKS * (THREADS / 32);   // 4736 warps, ~14 edges each

// One warp per edge, grid-stride, 3-stage software pipeline:
//   rows (x + nbr) in flight for edges k+1 AND k+2 while computing edge k,
//   idx prefetched at distance 3. Forces ~8 in-flight row loads per warp.
// out[e] = sum_f xi[f]*xj[f]*W[f] + sum_{d: ni[d] in nj} dot(x[ni[d]], W[F:2F]) + b
__global__ void __launch_bounds__(THREADS, 4)
ncn_kernel(const float* __restrict__ x,
           const int*   __restrict__ nbr,
           const int*   __restrict__ tar_ei,
           const float* __restrict__ W,
           const float* __restrict__ b,
           float*       __restrict__ out)
{
    const int lane = threadIdx.x & 31;
    const int w    = (blockIdx.x * blockDim.x + threadIdx.x) >> 5;

    const float4* xv = reinterpret_cast<const float4*>(x);

    // Per-lane weight slices (W is [256,1]): W0 = W[0:128], W1 = W[128:256]
    const float4 w0 = __ldg(&reinterpret_cast<const float4*>(W)[lane]);
    const float4 w1 = __ldg(&reinterpret_cast<const float4*>(W + F_DIM)[lane]);
    const float  bv = __ldg(b);

    // ---- pipeline prologue ----
    int e0 = w;                       // current edge (always < E at this config)
    int e1 = e0 + N_WARPS;
    int e2 = e1 + N_WARPS;
    int e3 = e2 + N_WARPS;

    const int ec1 = min(e1, E_EDGES - 1);
    const int ec2i = min(e2, E_EDGES - 1);

    // idx for e0..e2 (lane-invariant broadcast loads; clamped on tail)
    const int i0 = __ldg(tar_ei + e0);
    const int j0 = __ldg(tar_ei + E_EDGES + e0);
    int i1 = __ldg(tar_ei + ec1);
    int j1 = __ldg(tar_ei + E_EDGES + ec1);
    int i2 = __ldg(tar_ei + ec2i);
    int j2 = __ldg(tar_ei + E_EDGES + ec2i);

    // rows for e0 (stage 0) and e1 (stage 1)
    float4 a_c = __ldg(&xv[(size_t)i0 * (F_DIM/4) + lane]);
    float4 c_c = __ldg(&xv[(size_t)j0 * (F_DIM/4) + lane]);
    int   ni_c = __ldg(nbr + (size_t)i0 * D_DEG + lane);
    int   nj_c = __ldg(nbr + (size_t)j0 * D_DEG + lane);

    float4 a_1 = __ldg(&xv[(size_t)i1 * (F_DIM/4) + lane]);
    float4 c_1 = __ldg(&xv[(size_t)j1 * (F_DIM/4) + lane]);
    int   ni_1 = __ldg(nbr + (size_t)i1 * D_DEG + lane);
    int   nj_1 = __ldg(nbr + (size_t)j1 * D_DEG + lane);

    while (true) {
        // ---- stage: issue distance-2 row gathers (for e2) ----
        const float4 a_2 = __ldg(&xv[(size_t)i2 * (F_DIM/4) + lane]);
        const float4 c_2 = __ldg(&xv[(size_t)j2 * (F_DIM/4) + lane]);
        const int   ni_2 = __ldg(nbr + (size_t)i2 * D_DEG + lane);
        const int   nj_2 = __ldg(nbr + (size_t)j2 * D_DEG + lane);

        // ---- stage: issue distance-3 idx loads (for e3) ----
        const int ec3 = min(e3, E_EDGES - 1);
        const int i3  = __ldg(tar_ei + ec3);
        const int j3  = __ldg(tar_ei + E_EDGES + ec3);

        // ---- compute current edge e0 (rows already resident) ----
        float acc = a_c.x*c_c.x*w0.x + a_c.y*c_c.y*w0.y
                  + a_c.z*c_c.z*w0.z + a_c.w*c_c.w*w0.w;

        // lower_bound of ni_c in sorted distributed nj_c (clip + equality,
        // matching jnp.searchsorted semantics in the reference).
        int lo = 0, hi = D_DEG - 1;
        #pragma unroll
        for (int s = 0; s < 5; ++s) {
            const int mid = (lo + hi) >> 1;
            const int v   = __shfl_sync(FULL_MASK, nj_c, mid);
            if (v < ni_c) lo = mid + 1; else hi = mid;
        }
        const bool hit = (__shfl_sync(FULL_MASK, nj_c, lo) == ni_c);

        // Rare common-neighbor contributions (warp-uniform mask keeps convergence).
        unsigned hm = __ballot_sync(FULL_MASK, hit);
        while (hm) {
            const int h = __ffs(hm) - 1; hm &= hm - 1u;
            const int cn = __shfl_sync(FULL_MASK, ni_c, h);
            const float4 xc = __ldg(&xv[(size_t)cn * (F_DIM/4) + lane]);
            acc += xc.x*w1.x + xc.y*w1.y + xc.z*w1.z + xc.w*w1.w;
        }

        // Warp reduction (butterfly; plain-sm_100 PTX, no redux.f32).
        #pragma unroll
        for (int off = 16; off >= 1; off >>= 1)
            acc += __shfl_down_sync(FULL_MASK, acc, off);

        if (lane == 0) out[e0] = acc + bv;

        // ---- rotate pipeline ----
        if (e1 >= E_EDGES) break;
        e0 = e1; e1 = e2; e2 = e3; e3 += N_WARPS;
        a_c = a_1; c_c = c_1; ni_c = ni_1; nj_c = nj_1;
        a_1 = a_2; c_1 = c_2; ni_1 = ni_2; nj_1 = nj_2;
        i2 = i3; j2 = j3;
    }
}

extern "C" void kernel_launch(void* const* d_in, const int* in_sizes, int n_in,
                              void* d_out, int out_size)
{
    const float* x      = (const float*)d_in[0];
    const int*   nbr    = (const int*)  d_in[1];
    const int*   tar_ei = (const int*)  d_in[2];
    const float* W      = (const float*)d_in[3];
    const float* b      = (const float*)d_in[4];
    float*       out    = (float*)d_out;

    ncn_kernel<<<BLOCKS, THREADS>>>(x, nbr, tar_ei, W, b, out);
}

// round 11
// speedup vs baseline: 1.1054x; 1.1054x over previous
#include <cuda_runtime.h>
#include <cuda_bf16.h>
#include <cstdint>

#define FULL_MASK 0xFFFFFFFFu

constexpr int E_EDGES = 65536;
constexpr int F_DIM   = 128;
constexpr int D_DEG   = 32;
constexpr int BLOCKS  = 1184;     // R1 shape: ~7 edges per warp grid-stride
constexpr int THREADS = 256;
constexpr int N_WARPS = BLOCKS * (THREADS / 32);   // 9472 warps

// One warp per edge, grid-stride, with ONLY the next edge's index pair
// prefetched (distance 1). Keeps regs ~36 so occupancy stays high, while
// removing the idx->row load serialization from the per-edge chain.
// out[e] = sum_f xi[f]*xj[f]*W[f] + sum_{d: ni[d] in nj} dot(x[ni[d]], W[F:2F]) + b
__global__ void __launch_bounds__(THREADS, 7)
ncn_kernel(const float* __restrict__ x,
           const int*   __restrict__ nbr,
           const int*   __restrict__ tar_ei,
           const float* __restrict__ W,
           const float* __restrict__ b,
           float*       __restrict__ out)
{
    const int lane = threadIdx.x & 31;
    const int w    = (blockIdx.x * blockDim.x + threadIdx.x) >> 5;

    const float4* xv = reinterpret_cast<const float4*>(x);

    // Per-lane weight slices (W is [256,1]): W0 = W[0:128], W1 = W[128:256]
    const float4 w0 = __ldg(&reinterpret_cast<const float4*>(W)[lane]);
    const float4 w1 = __ldg(&reinterpret_cast<const float4*>(W + F_DIM)[lane]);
    const float  bv = __ldg(b);

    // Prologue: load idx for the first edge this warp owns.
    int e   = w;
    int i_c = __ldg(tar_ei + e);
    int j_c = __ldg(tar_ei + E_EDGES + e);

    while (true) {
        // Issue current edge's row gathers immediately (idx already resident).
        const float4 a   = __ldg(&xv[(size_t)i_c * (F_DIM/4) + lane]);
        const float4 c   = __ldg(&xv[(size_t)j_c * (F_DIM/4) + lane]);
        const int   ni_l = __ldg(nbr + (size_t)i_c * D_DEG + lane);
        const int   nj_l = __ldg(nbr + (size_t)j_c * D_DEG + lane);

        // Prefetch next edge's idx pair (overlaps with this edge's gathers+compute).
        const int e_n  = e + N_WARPS;
        const int ec_n = min(e_n, E_EDGES - 1);
        const int i_n  = __ldg(tar_ei + ec_n);
        const int j_n  = __ldg(tar_ei + E_EDGES + ec_n);

        // (xi * xj) . W0, per-lane partial
        float acc = a.x*c.x*w0.x + a.y*c.y*w0.y + a.z*c.z*w0.z + a.w*c.w*w0.w;

        // lower_bound of ni_l in sorted distributed nj (clip + equality,
        // matching jnp.searchsorted semantics in the reference).
        int lo = 0, hi = D_DEG - 1;
        #pragma unroll
        for (int s = 0; s < 5; ++s) {
            const int mid = (lo + hi) >> 1;
            const int v   = __shfl_sync(FULL_MASK, nj_l, mid);
            if (v < ni_l) lo = mid + 1; else hi = mid;
        }
        const bool hit = (__shfl_sync(FULL_MASK, nj_l, lo) == ni_l);

        // Rare common-neighbor contributions (warp-uniform mask keeps convergence).
        unsigned hm = __ballot_sync(FULL_MASK, hit);
        while (hm) {
            const int h = __ffs(hm) - 1; hm &= hm - 1u;
            const int cn = __shfl_sync(FULL_MASK, ni_l, h);
            const float4 xc = __ldg(&xv[(size_t)cn * (F_DIM/4) + lane]);
            acc += xc.x*w1.x + xc.y*w1.y + xc.z*w1.z + xc.w*w1.w;
        }

        // Warp reduction (butterfly).
        #pragma unroll
        for (int off = 16; off >= 1; off >>= 1)
            acc += __shfl_down_sync(FULL_MASK, acc, off);

        if (lane == 0) out[e] = acc + bv;

        if (e_n >= E_EDGES) break;
        e = e_n; i_c = i_n; j_c = j_n;
    }
}

extern "C" void kernel_launch(void* const* d_in, const int* in_sizes, int n_in,
                              void* d_out, int out_size)
{
    const float* x      = (const float*)d_in[0];
    const int*   nbr    = (const int*)  d_in[1];
    const int*   tar_ei = (const int*)  d_in[2];
    const float* W      = (const float*)d_in[3];
    const float* b      = (const float*)d_in[4];
    float*       out    = (float*)d_out;

    ncn_kernel<<<BLOCKS, THREADS>>>(x, nbr, tar_ei, W, b, out);
}